// round 11
// baseline (speedup 1.0000x reference)
#include <cuda_runtime.h>

typedef unsigned int u32;
typedef unsigned short u16;

#define CCH  192
#define HWSZ 16384
#define NTHR 384
#define EPSV 1e-6f

// ---- smem byte offsets ----
#define OFF_AH 0u          // A hi: 128px x 192ch bf16, 384B/row, XOR16 swizzle
#define OFF_AL 49152u      // A lo
#define OFF_TH 98304u      // T (q then t) hi   (gate partials overlay early)
#define OFF_TL 147456u     // T lo
#define OFF_W  196608u     // 2 x 12288B weight k-step buffers (192ch x 16k hi|lo)
#define OFF_GS 221184u     // gates 3x128 f32
#define OFF_FB 222720u     // fb 196 f32
#define OFF_HB 223504u
#define OFF_PB 224272u
#define OFF_LW 225040u
#define OFF_LB 225808u
#define OFF_MU 226576u
#define OFF_RS 227088u
#define SMEM_TOTAL 227600
// py (fp32 y, [ch][128px] stride 512B, swizzled) overlays OFF_AH..98304
// LN partials overlay OFF_W

// 36 regions = 3 gemms x 12 k-steps; each 192 rows x 64B = 12288B. 442368 B.
__device__ __align__(16) u16 g_wc[221184];

__device__ __forceinline__ u32 cvt2(float lo, float hi) {
    u32 r; asm("cvt.rn.bf16x2.f32 %0, %1, %2;" : "=r"(r) : "f"(hi), "f"(lo)); return r;
}
__device__ __forceinline__ void split2(float a, float b, u32& h2, u32& l2) {
    h2 = cvt2(a, b);
    float ah = __uint_as_float(h2 << 16);
    float bh = __uint_as_float(h2 & 0xFFFF0000u);
    l2 = cvt2(a - ah, b - bh);
}
__device__ __forceinline__ u32 smem_u32_of(const void* p) {
    u32 a;
    asm("{ .reg .u64 t; cvta.to.shared.u64 t, %1; cvt.u32.u64 %0, t; }" : "=r"(a) : "l"(p));
    return a;
}
__device__ __forceinline__ void ldsm4(u32& r0, u32& r1, u32& r2, u32& r3, u32 a) {
    asm volatile("ldmatrix.sync.aligned.m8n8.x4.shared.b16 {%0,%1,%2,%3}, [%4];"
                 : "=r"(r0), "=r"(r1), "=r"(r2), "=r"(r3) : "r"(a));
}
__device__ __forceinline__ void mma16816(float* d, u32 a0, u32 a1, u32 a2, u32 a3,
                                         u32 b0, u32 b1) {
    asm volatile(
        "mma.sync.aligned.m16n8k16.row.col.f32.bf16.bf16.f32 "
        "{%0,%1,%2,%3}, {%4,%5,%6,%7}, {%8,%9}, {%0,%1,%2,%3};"
        : "+f"(d[0]), "+f"(d[1]), "+f"(d[2]), "+f"(d[3])
        : "r"(a0), "r"(a1), "r"(a2), "r"(a3), "r"(b0), "r"(b1));
}

// ---- pre-kernel: fp32 weights -> bf16 hi/lo, 36 k-step regions ----
// region = g*12 + (k>>4); row r = out-channel; within row (64B):
//   u = (kk>>3) for hi, 2+(kk>>3) for lo; byte = r*64 + ((u ^ ((r>>1)&3))<<4) + (kk&7)*2
__global__ void CM_wconv_kernel(const float* __restrict__ fw,
                                const float* __restrict__ hwm,
                                const float* __restrict__ pw) {
    int idx = blockIdx.x * 256 + threadIdx.x;
    if (idx >= 3 * 192 * 192) return;
    int g = idx / (192 * 192);
    int rem = idx - g * (192 * 192);
    int r = rem / 192, k = rem - (rem / 192) * 192;
    const float* src = (g == 0) ? fw : (g == 1) ? hwm : pw;
    float w = src[r * 192 + k];
    u32 h2 = cvt2(w, 0.f);
    float hf = __uint_as_float(h2 << 16);
    u32 l2 = cvt2(w - hf, 0.f);
    int region = g * 12 + (k >> 4);
    int kk = k & 15;
    u32 base = (u32)region * 12288u + (u32)r * 64u + (u32)(kk & 7) * 2u;
    u32 sw = ((u32)(r >> 1) & 3u);
    u32 uh = (u32)(kk >> 3);
    u32 ul = uh + 2u;
    g_wc[(base + ((uh ^ sw) << 4)) >> 1] = (u16)(h2 & 0xFFFFu);
    g_wc[(base + ((ul ^ sw) << 4)) >> 1] = (u16)(l2 & 0xFFFFu);
}

// full GEMM over K=192: 12 k-steps, ping-pong weight staging, Mt=4 x Nt=4
__device__ __forceinline__ void gemm_full(char* smem, u32 smb, u32 offH, u32 offL,
                                          int base, float (&acc)[64],
                                          int wm, int wn, int lane, int t) {
    const uint4* gw = (const uint4*)g_wc;
    // prologue: stage region `base` -> buf0, prefetch base+1
    uint4 p0 = gw[(size_t)base * 768 + t];
    uint4 p1 = gw[(size_t)base * 768 + t + 384];
    ((uint4*)(smem + OFF_W))[t]       = p0;
    ((uint4*)(smem + OFF_W))[t + 384] = p1;
    p0 = gw[(size_t)(base + 1) * 768 + t];
    p1 = gw[(size_t)(base + 1) * 768 + t + 384];
    __syncthreads();

    const u32 aswz = (u32)(lane & 7) << 4;
    const u32 axor = ((u32)(lane >> 4) & 1u) * 16u;
    const u32 abase = ((u32)(64 * wm) + (u32)(lane & 7) + ((u32)(lane >> 3) & 1u) * 8u) * 384u;
    const u32 abh = smb + offH + abase;
    const u32 abl = smb + offL + abase;
    // B per-lane offset: row-in-8 = lane&7, u = hi/lo + k-half, slot swizzle
    const u32 uu = ((u32)(lane >> 4) & 1u) * 2u + ((u32)(lane >> 3) & 1u);
    const u32 bloff = (u32)(lane & 7) * 64u + ((uu ^ (((u32)lane >> 1) & 3u)) << 4);
    const u32 bwarp = (u32)wn * 2048u + bloff;

    #pragma unroll 1
    for (int ks = 0; ks < 12; ++ks) {
        u32 wcur = OFF_W + (u32)(ks & 1) * 12288u;
        if (ks < 11) {
            u32 wnxt = OFF_W + (u32)((ks + 1) & 1) * 12288u;
            ((uint4*)(smem + wnxt))[t]       = p0;
            ((uint4*)(smem + wnxt))[t + 384] = p1;
            if (ks < 10) {
                p0 = gw[(size_t)(base + ks + 2) * 768 + t];
                p1 = gw[(size_t)(base + ks + 2) * 768 + t + 384];
            }
        }
        u32 acol = (32u * (u32)ks + axor) ^ aswz;
        u32 fa[32];
        #pragma unroll
        for (int mt = 0; mt < 4; ++mt) {
            u32 off = (u32)(16 * mt) * 384u + acol;
            ldsm4(fa[8*mt+0], fa[8*mt+1], fa[8*mt+2], fa[8*mt+3], abh + off);
            ldsm4(fa[8*mt+4], fa[8*mt+5], fa[8*mt+6], fa[8*mt+7], abl + off);
        }
        u32 fb[16];
        u32 bb = smb + wcur + bwarp;
        ldsm4(fb[0],  fb[1],  fb[2],  fb[3],  bb);
        ldsm4(fb[4],  fb[5],  fb[6],  fb[7],  bb + 512u);
        ldsm4(fb[8],  fb[9],  fb[10], fb[11], bb + 1024u);
        ldsm4(fb[12], fb[13], fb[14], fb[15], bb + 1536u);
        #pragma unroll
        for (int mt = 0; mt < 4; ++mt)
            #pragma unroll
            for (int nt = 0; nt < 4; ++nt) {
                float* a = &acc[(mt * 4 + nt) * 4];
                mma16816(a, fa[8*mt+0], fa[8*mt+1], fa[8*mt+2], fa[8*mt+3],
                         fb[4*nt+0], fb[4*nt+1]);                          // hh
                mma16816(a, fa[8*mt+0], fa[8*mt+1], fa[8*mt+2], fa[8*mt+3],
                         fb[4*nt+2], fb[4*nt+3]);                          // h*lo(B)
                mma16816(a, fa[8*mt+4], fa[8*mt+5], fa[8*mt+6], fa[8*mt+7],
                         fb[4*nt+0], fb[4*nt+1]);                          // lo(A)*h
            }
        __syncthreads();
    }
}

__global__ void __launch_bounds__(NTHR)
CM_29540785062535_kernel(const float* __restrict__ x,
                         const float* __restrict__ xl,
                         const float* __restrict__ fw,
                         const float* __restrict__ fbg,
                         const float* __restrict__ hbg,
                         const float* __restrict__ pbg,
                         const float* __restrict__ lnwg,
                         const float* __restrict__ lnbg,
                         float* __restrict__ out,
                         int Nn)
{
    extern __shared__ char smem[];
    const u32 smb = smem_u32_of(smem);
    const int t    = threadIdx.x;
    const int lane = t & 31;
    const int w    = t >> 5;
    const int wm   = w & 1;        // 2 M positions (64px each)
    const int wn   = w >> 1;       // 6 N positions (32ch each) -> full 192

    const int n   = blockIdx.x >> 7;
    const int hw0 = (blockIdx.x & 127) << 7;

    float* sfb = (float*)(smem + OFF_FB);
    float* shb = (float*)(smem + OFF_HB);
    float* spb = (float*)(smem + OFF_PB);
    float* slw = (float*)(smem + OFF_LW);
    float* slb = (float*)(smem + OFF_LB);
    float* gsf = (float*)(smem + OFF_GS);
    float* mus = (float*)(smem + OFF_MU);
    float* rss = (float*)(smem + OFF_RS);

    for (int i = t; i < 195; i += NTHR) sfb[i] = fbg[i];
    for (int i = t; i < 192; i += NTHR) {
        shb[i] = hbg[i]; spb[i] = pbg[i]; slw[i] = lnwg[i]; slb[i] = lnbg[i];
    }

    const int px4 = t & 31;
    const int cpb = t >> 5;

    // ---- phase 1: stage x -> AH/AL + gate partials (overlay TH) ----
    {
        const float* xb = x + ((size_t)n * CCH) * HWSZ + hw0;
        float* gpart = (float*)(smem + OFF_TH);
        float ga[12];
        #pragma unroll
        for (int m = 0; m < 12; ++m) ga[m] = 0.f;
        #pragma unroll 2
        for (int j = 0; j < 8; ++j) {
            int cp = cpb + 12 * j;
            int c = 2 * cp;
            float4 a = *(const float4*)(xb + (size_t)c * HWSZ + 4 * px4);
            float4 b = *(const float4*)(xb + (size_t)(c + 1) * HWSZ + 4 * px4);
            float av[4] = {a.x, a.y, a.z, a.w};
            float bv[4] = {b.x, b.y, b.z, b.w};
            #pragma unroll
            for (int jj = 0; jj < 4; ++jj) {
                u32 h2, l2;
                split2(av[jj], bv[jj], h2, l2);
                u32 px = (u32)(4 * px4 + jj);
                u32 off = px * 384u + (((u32)(2 * c)) ^ ((px & 7u) << 4));
                *(u32*)(smem + OFF_AH + off) = h2;
                *(u32*)(smem + OFF_AL + off) = l2;
            }
            #pragma unroll
            for (int l = 0; l < 3; ++l) {
                float w0 = __ldg(fw + (size_t)(192 + l) * 192 + c);
                float w1 = __ldg(fw + (size_t)(192 + l) * 192 + c + 1);
                #pragma unroll
                for (int jj = 0; jj < 4; ++jj)
                    ga[l * 4 + jj] = fmaf(w0, av[jj], fmaf(w1, bv[jj], ga[l * 4 + jj]));
            }
        }
        #pragma unroll
        for (int l = 0; l < 3; ++l)
            #pragma unroll
            for (int jj = 0; jj < 4; ++jj)
                gpart[cpb * 384 + l * 128 + 4 * px4 + jj] = ga[l * 4 + jj];
    }
    __syncthreads();
    {
        const float* gpart = (const float*)(smem + OFF_TH);
        float v = sfb[192 + (t >> 7)];
        #pragma unroll
        for (int g = 0; g < 12; ++g) v += gpart[g * 384 + t];
        gsf[t] = v;
    }
    __syncthreads();

    const int tq = lane & 3;
    const int gg = lane >> 2;

    float acc[64];

    // ---- GEMM1: q = x @ fw ; q+fb -> TH/TL ----
    #pragma unroll
    for (int m = 0; m < 64; ++m) acc[m] = 0.f;
    gemm_full(smem, smb, OFF_AH, OFF_AL, 0, acc, wm, wn, lane, t);
    #pragma unroll
    for (int mt = 0; mt < 4; ++mt)
        #pragma unroll
        for (int nt = 0; nt < 4; ++nt) {
            int ch0 = 32 * wn + 8 * nt + 2 * tq;
            int r0 = 64 * wm + 16 * mt + gg;
            const float* a = &acc[(mt * 4 + nt) * 4];
            u32 o0 = (u32)r0 * 384u + (((u32)(2 * ch0)) ^ (((u32)r0 & 7u) << 4));
            u32 o1 = o0 + 8u * 384u;
            u32 h2, l2;
            split2(a[0] + sfb[ch0], a[1] + sfb[ch0 + 1], h2, l2);
            *(u32*)(smem + OFF_TH + o0) = h2;
            *(u32*)(smem + OFF_TL + o0) = l2;
            split2(a[2] + sfb[ch0], a[3] + sfb[ch0 + 1], h2, l2);
            *(u32*)(smem + OFF_TH + o1) = h2;
            *(u32*)(smem + OFF_TL + o1) = l2;
        }

    // ---- ctx = sum_l gates[l]*x_list[l] -> AH/AL ----
    // (safe: all GEMM1 A-reads completed before gemm_full's final sync)
    {
        const float* b0 = xl + ((size_t)(0 * Nn + n) * CCH) * HWSZ + hw0;
        const float* b1 = xl + ((size_t)(1 * Nn + n) * CCH) * HWSZ + hw0;
        const float* b2 = xl + ((size_t)(2 * Nn + n) * CCH) * HWSZ + hw0;
        float4 g0 = *(const float4*)(gsf + 0 * 128 + 4 * px4);
        float4 g1 = *(const float4*)(gsf + 1 * 128 + 4 * px4);
        float4 g2 = *(const float4*)(gsf + 2 * 128 + 4 * px4);
        float g0v[4] = {g0.x, g0.y, g0.z, g0.w};
        float g1v[4] = {g1.x, g1.y, g1.z, g1.w};
        float g2v[4] = {g2.x, g2.y, g2.z, g2.w};
        #pragma unroll 2
        for (int j = 0; j < 8; ++j) {
            int cp = cpb + 12 * j;
            int c = 2 * cp;
            size_t oa = (size_t)c * HWSZ + 4 * px4;
            size_t ob = oa + HWSZ;
            float4 a0 = *(const float4*)(b0 + oa), a1 = *(const float4*)(b1 + oa), a2 = *(const float4*)(b2 + oa);
            float4 c0 = *(const float4*)(b0 + ob), c1 = *(const float4*)(b1 + ob), c2 = *(const float4*)(b2 + ob);
            float a0v[4] = {a0.x, a0.y, a0.z, a0.w};
            float a1v[4] = {a1.x, a1.y, a1.z, a1.w};
            float a2v[4] = {a2.x, a2.y, a2.z, a2.w};
            float c0v[4] = {c0.x, c0.y, c0.z, c0.w};
            float c1v[4] = {c1.x, c1.y, c1.z, c1.w};
            float c2v[4] = {c2.x, c2.y, c2.z, c2.w};
            #pragma unroll
            for (int jj = 0; jj < 4; ++jj) {
                float va = fmaf(g2v[jj], a2v[jj], fmaf(g1v[jj], a1v[jj], g0v[jj] * a0v[jj]));
                float vb = fmaf(g2v[jj], c2v[jj], fmaf(g1v[jj], c1v[jj], g0v[jj] * c0v[jj]));
                u32 h2, l2;
                split2(va, vb, h2, l2);
                u32 px = (u32)(4 * px4 + jj);
                u32 off = px * 384u + (((u32)(2 * c)) ^ ((px & 7u) << 4));
                *(u32*)(smem + OFF_AH + off) = h2;
                *(u32*)(smem + OFF_AL + off) = l2;
            }
        }
    }
    // GEMM2 prologue's sync orders ctx writes before its A-reads

    // ---- GEMM2: mod = ctx @ hw ; t = q*(mod+hb) -> TH/TL in place ----
    #pragma unroll
    for (int m = 0; m < 64; ++m) acc[m] = 0.f;
    gemm_full(smem, smb, OFF_AH, OFF_AL, 12, acc, wm, wn, lane, t);
    #pragma unroll
    for (int mt = 0; mt < 4; ++mt)
        #pragma unroll
        for (int nt = 0; nt < 4; ++nt) {
            int ch0 = 32 * wn + 8 * nt + 2 * tq;
            int r0 = 64 * wm + 16 * mt + gg;
            const float* a = &acc[(mt * 4 + nt) * 4];
            u32 o0 = (u32)r0 * 384u + (((u32)(2 * ch0)) ^ (((u32)r0 & 7u) << 4));
            u32 o1 = o0 + 8u * 384u;
            u32 qh = *(u32*)(smem + OFF_TH + o0);
            u32 ql = *(u32*)(smem + OFF_TL + o0);
            float q0 = __uint_as_float(qh << 16) + __uint_as_float(ql << 16);
            float q1 = __uint_as_float(qh & 0xFFFF0000u) + __uint_as_float(ql & 0xFFFF0000u);
            float t0 = q0 * (a[0] + shb[ch0]);
            float t1 = q1 * (a[1] + shb[ch0 + 1]);
            u32 h2, l2;
            split2(t0, t1, h2, l2);
            *(u32*)(smem + OFF_TH + o0) = h2;
            *(u32*)(smem + OFF_TL + o0) = l2;
            qh = *(u32*)(smem + OFF_TH + o1);
            ql = *(u32*)(smem + OFF_TL + o1);
            q0 = __uint_as_float(qh << 16) + __uint_as_float(ql << 16);
            q1 = __uint_as_float(qh & 0xFFFF0000u) + __uint_as_float(ql & 0xFFFF0000u);
            t0 = q0 * (a[2] + shb[ch0]);
            t1 = q1 * (a[3] + shb[ch0 + 1]);
            split2(t0, t1, h2, l2);
            *(u32*)(smem + OFF_TH + o1) = h2;
            *(u32*)(smem + OFF_TL + o1) = l2;
        }
    // GEMM3 prologue's sync orders t-writes before its T-reads

    // ---- GEMM3: y = t @ pw ; y+pb -> py fp32 [ch][128px] (overlays A) ----
    #pragma unroll
    for (int m = 0; m < 64; ++m) acc[m] = 0.f;
    gemm_full(smem, smb, OFF_TH, OFF_TL, 24, acc, wm, wn, lane, t);
    #pragma unroll
    for (int mt = 0; mt < 4; ++mt)
        #pragma unroll
        for (int nt = 0; nt < 4; ++nt) {
            int ch0 = 32 * wn + 8 * nt + 2 * tq;
            int r0 = 64 * wm + 16 * mt + gg;
            int r1 = r0 + 8;
            const float* a = &acc[(mt * 4 + nt) * 4];
            u32 s0 = (u32)ch0 * 512u + (((u32)(4 * r0)) ^ (((u32)ch0 & 7u) << 4));
            u32 s1 = (u32)(ch0 + 1) * 512u + (((u32)(4 * r0)) ^ (((u32)(ch0 + 1) & 7u) << 4));
            u32 s2 = (u32)ch0 * 512u + (((u32)(4 * r1)) ^ (((u32)ch0 & 7u) << 4));
            u32 s3 = (u32)(ch0 + 1) * 512u + (((u32)(4 * r1)) ^ (((u32)(ch0 + 1) & 7u) << 4));
            *(float*)(smem + s0) = a[0] + spb[ch0];
            *(float*)(smem + s1) = a[1] + spb[ch0 + 1];
            *(float*)(smem + s2) = a[2] + spb[ch0];
            *(float*)(smem + s3) = a[3] + spb[ch0 + 1];
        }
    __syncthreads();

    // ---- LN stats: 3 segs x 128 px (partials overlay W) ----
    {
        float* ps = (float*)(smem + OFF_W);
        float* qs = ps + 384;
        int seg = t >> 7, px = t & 127;
        float s = 0.f, s2 = 0.f;
        #pragma unroll 4
        for (int ch = 64 * seg; ch < 64 * seg + 64; ++ch) {
            float v = *(float*)(smem + (u32)ch * 512u + (((u32)(4 * px)) ^ (((u32)ch & 7u) << 4)));
            s += v;
            s2 = fmaf(v, v, s2);
        }
        ps[t] = s; qs[t] = s2;
    }
    __syncthreads();
    if (t < 128) {
        float* ps = (float*)(smem + OFF_W);
        float* qs = ps + 384;
        float st = ps[t] + ps[t + 128] + ps[t + 256];
        float qt = qs[t] + qs[t + 128] + qs[t + 256];
        float mu  = st * (1.0f / CCH);
        float var = qt * (1.0f / CCH) - mu * mu;
        mus[t] = mu;
        rss[t] = rsqrtf(var + EPSV);
    }
    __syncthreads();

    // ---- normalize + residual + coalesced store ----
    {
        const float* xb = x + ((size_t)n * CCH) * HWSZ + hw0;
        float* ob = out + ((size_t)n * CCH) * HWSZ + hw0;
        #pragma unroll 4
        for (int u = 0; u < 16; ++u) {
            int f4 = t + 384 * u;
            int c = f4 >> 5, L = f4 & 31;
            float4 y = *(const float4*)(smem + (u32)c * 512u + (((u32)(16 * L)) ^ (((u32)c & 7u) << 4)));
            float4 xv = *(const float4*)(xb + (size_t)c * HWSZ + 4 * L);
            float4 m = *(const float4*)(mus + 4 * L);
            float4 r = *(const float4*)(rss + 4 * L);
            float lw = slw[c], lb = slb[c];
            float4 o;
            o.x = fmaf(lw * (y.x - m.x), r.x, lb) + xv.x;
            o.y = fmaf(lw * (y.y - m.y), r.y, lb) + xv.y;
            o.z = fmaf(lw * (y.z - m.z), r.z, lb) + xv.z;
            o.w = fmaf(lw * (y.w - m.w), r.w, lb) + xv.w;
            *(float4*)(ob + (size_t)c * HWSZ + 4 * L) = o;
        }
    }
}

extern "C" void kernel_launch(void* const* d_in, const int* in_sizes, int n_in,
                              void* d_out, int out_size) {
    const float* x   = (const float*)d_in[0];
    const float* xl  = (const float*)d_in[1];
    const float* fw  = (const float*)d_in[2];
    const float* fb  = (const float*)d_in[3];
    const float* hwm = (const float*)d_in[4];
    const float* hb  = (const float*)d_in[5];
    const float* pw  = (const float*)d_in[6];
    const float* pb  = (const float*)d_in[7];
    const float* lnw = (const float*)d_in[8];
    const float* lnb = (const float*)d_in[9];
    float* out = (float*)d_out;

    int Nn = in_sizes[0] / (CCH * HWSZ);

    CM_wconv_kernel<<<(3 * 192 * 192 + 255) / 256, 256>>>(fw, hwm, pw);

    cudaFuncSetAttribute(CM_29540785062535_kernel,
                         cudaFuncAttributeMaxDynamicSharedMemorySize, SMEM_TOTAL);

    int blocks = Nn * (HWSZ / 128);   // 2048
    CM_29540785062535_kernel<<<blocks, NTHR, SMEM_TOTAL>>>(
        x, xl, fw, fb, hb, pb, lnw, lnb, out, Nn);
}